// round 1
// baseline (speedup 1.0000x reference)
#include <cuda_runtime.h>
#include <math.h>

#define NB 2
#define BB 4
#define TT 2048
#define DD 128
#define HH 4
#define DK 32
#define ROWS (BB*TT)          // 8192
#define LN_EPS 1e-3f

// -------------------- scratch (device globals; no allocs allowed) ------------
__device__ float g_h  [ROWS*DD];
__device__ float g_hn [ROWS*DD];
__device__ float g_q  [ROWS*DD];
__device__ float g_k  [ROWS*DD];
__device__ float g_v  [ROWS*DD];
__device__ float g_ctx[ROWS*DD];
__device__ float g_tmp[ROWS*DD];
__device__ float g_pe [TT*DD];

// -------------------- positional encoding (fp64, matches numpy) --------------
__global__ void pe_kernel(float* __restrict__ pe) {
    int i = blockIdx.x;  // feature index 0..127
    // 10000^(-2i/128) = exp(-(2i/128)*ln(10000))
    double f = exp(-((double)(2 * i) / 128.0) * 9.210340371976184);
    for (int t = threadIdx.x; t < TT; t += blockDim.x) {
        double ang = (double)t * f;
        double val = (i & 1) ? cos(ang) : sin(ang);
        pe[t * DD + i] = (float)val;
    }
}

// -------------------- h = inputs + pe ----------------------------------------
__global__ void addpos_kernel(const float* __restrict__ in, const float* __restrict__ pe,
                              float* __restrict__ h) {
    int gi = blockIdx.x * blockDim.x + threadIdx.x;   // float4 index, 262144 total
    const float4* in4 = (const float4*)in;
    const float4* pe4 = (const float4*)pe;
    float4 a = in4[gi];
    float4 p = pe4[gi & ((TT * DD / 4) - 1)];
    a.x += p.x; a.y += p.y; a.z += p.z; a.w += p.w;
    ((float4*)h)[gi] = a;
}

// -------------------- LayerNorm: one warp per 128-wide row --------------------
__global__ void ln_kernel(const float* __restrict__ x, const float* __restrict__ g,
                          const float* __restrict__ b, float* __restrict__ y) {
    int row  = blockIdx.x * 8 + (threadIdx.x >> 5);
    int lane = threadIdx.x & 31;
    float4 xv = ((const float4*)x)[row * 32 + lane];
    float s = xv.x + xv.y + xv.z + xv.w;
    #pragma unroll
    for (int o = 16; o > 0; o >>= 1) s += __shfl_xor_sync(0xffffffff, s, o);
    float mu = s * (1.0f / 128.0f);
    float dx0 = xv.x - mu, dx1 = xv.y - mu, dx2 = xv.z - mu, dx3 = xv.w - mu;
    float sq = dx0*dx0 + dx1*dx1 + dx2*dx2 + dx3*dx3;
    #pragma unroll
    for (int o = 16; o > 0; o >>= 1) sq += __shfl_xor_sync(0xffffffff, sq, o);
    float var = sq * (1.0f / 128.0f);
    float r = rsqrtf(var + LN_EPS);
    float4 gv = ((const float4*)g)[lane];
    float4 bv = ((const float4*)b)[lane];
    float4 ov;
    ov.x = gv.x * dx0 * r + bv.x;
    ov.y = gv.y * dx1 * r + bv.y;
    ov.z = gv.z * dx2 * r + bv.z;
    ov.w = gv.w * dx3 * r + bv.w;
    ((float4*)y)[row * 32 + lane] = ov;
}

// -------------------- GEMM C[8192,128] = A[8192,128] @ W[128,128] + bias -----
// MODE: 0 plain, 1 relu, 2 +residual R, 3 scatter to [B,H,T,DK]
template <int MODE>
__global__ __launch_bounds__(256) void gemm128_kernel(
        const float* __restrict__ A, const float* __restrict__ W,
        const float* __restrict__ bias, const float* __restrict__ R,
        float* __restrict__ C) {
    __shared__ float As[64][33];
    __shared__ float Ws[32][128];
    int tid = threadIdx.x;
    int tx = tid & 31;      // -> N
    int ty = tid >> 5;      // -> M
    int m0 = blockIdx.x * 64;
    float acc[8][4] = {};

    for (int k0 = 0; k0 < 128; k0 += 32) {
        #pragma unroll
        for (int l = 0; l < 2; l++) {
            int e = tid + l * 256;            // 0..511 float4s of A tile
            int m = e >> 3, kv = e & 7;
            float4 av = *(const float4*)&A[(m0 + m) * 128 + k0 + kv * 4];
            As[m][kv*4+0] = av.x; As[m][kv*4+1] = av.y;
            As[m][kv*4+2] = av.z; As[m][kv*4+3] = av.w;
        }
        #pragma unroll
        for (int l = 0; l < 4; l++) {
            int e = tid + l * 256;            // 0..1023 float4s of W tile
            int kk = e >> 5, nv = e & 31;
            *(float4*)&Ws[kk][nv * 4] = *(const float4*)&W[(k0 + kk) * 128 + nv * 4];
        }
        __syncthreads();
        #pragma unroll
        for (int kk = 0; kk < 32; kk++) {
            float4 wv = *(const float4*)&Ws[kk][tx * 4];
            #pragma unroll
            for (int r = 0; r < 8; r++) {
                float a = As[ty * 8 + r][kk];
                acc[r][0] += a * wv.x; acc[r][1] += a * wv.y;
                acc[r][2] += a * wv.z; acc[r][3] += a * wv.w;
            }
        }
        __syncthreads();
    }

    int n = tx * 4;
    float4 bv = *(const float4*)&bias[n];
    #pragma unroll
    for (int r = 0; r < 8; r++) {
        int m = m0 + ty * 8 + r;
        float4 o;
        o.x = acc[r][0] + bv.x; o.y = acc[r][1] + bv.y;
        o.z = acc[r][2] + bv.z; o.w = acc[r][3] + bv.w;
        if (MODE == 1) {
            o.x = fmaxf(o.x, 0.f); o.y = fmaxf(o.y, 0.f);
            o.z = fmaxf(o.z, 0.f); o.w = fmaxf(o.w, 0.f);
        }
        if (MODE == 2) {
            float4 rv = *(const float4*)&R[m * 128 + n];
            o.x += rv.x; o.y += rv.y; o.z += rv.z; o.w += rv.w;
        }
        if (MODE == 3) {
            int b = m >> 11, t = m & 2047, hh = n >> 5, dk = n & 31;
            *(float4*)&C[(((b << 2) + hh) * 2048 + t) * 32 + dk] = o;
        } else {
            *(float4*)&C[m * 128 + n] = o;
        }
    }
}

// -------------------- flash attention: thread-per-query, DK=32 ---------------
// Q,K,V in [B*H, T, 32]; ctx written in [B, T, D]
__global__ __launch_bounds__(128) void attn_kernel(
        const float* __restrict__ Q, const float* __restrict__ K,
        const float* __restrict__ V, float* __restrict__ ctx) {
    __shared__ float Ks[128 * 32];
    __shared__ float Vs[128 * 32];
    int bid = blockIdx.x;      // 0..255
    int bh  = bid >> 4;        // 0..15 = b*4+h
    int qc  = bid & 15;
    int tid = threadIdx.x;     // 0..127

    const float scale = 0.17677669529663687f;  // 1/sqrt(32)
    float qr[32];
    {
        const float4* q4 = (const float4*)(Q + (size_t)(bh * TT + qc * 128 + tid) * 32);
        #pragma unroll
        for (int i = 0; i < 8; i++) {
            float4 t = q4[i];
            qr[i*4+0] = t.x * scale; qr[i*4+1] = t.y * scale;
            qr[i*4+2] = t.z * scale; qr[i*4+3] = t.w * scale;
        }
    }
    float m = -1e30f, l = 0.f;
    float o[32];
    #pragma unroll
    for (int d = 0; d < 32; d++) o[d] = 0.f;

    const float4* Kb = (const float4*)(K + (size_t)bh * TT * 32);
    const float4* Vb = (const float4*)(V + (size_t)bh * TT * 32);
    float4* kd = (float4*)Ks;
    float4* vd = (float4*)Vs;

    for (int t0 = 0; t0 < TT; t0 += 128) {
        int base = t0 * 8;     // float4s
        #pragma unroll
        for (int i = 0; i < 8; i++) {
            kd[tid + i * 128] = Kb[base + tid + i * 128];
            vd[tid + i * 128] = Vb[base + tid + i * 128];
        }
        __syncthreads();
        for (int j = 0; j < 128; j++) {
            const float* kj = Ks + j * 32;
            float s = 0.f;
            #pragma unroll
            for (int d = 0; d < 32; d++) s += qr[d] * kj[d];
            float mn = fmaxf(m, s);
            if (mn > m) {
                float c = __expf(m - mn);
                l *= c;
                #pragma unroll
                for (int d = 0; d < 32; d++) o[d] *= c;
                m = mn;
            }
            float p = __expf(s - m);
            l += p;
            const float* vj = Vs + j * 32;
            #pragma unroll
            for (int d = 0; d < 32; d++) o[d] += p * vj[d];
        }
        __syncthreads();
    }
    float inv = 1.0f / l;
    int b = bh >> 2, hh = bh & 3, t = qc * 128 + tid;
    float4* dst = (float4*)(ctx + (size_t)(b * TT + t) * 128 + hh * 32);
    #pragma unroll
    for (int i = 0; i < 8; i++) {
        float4 ov;
        ov.x = o[i*4+0] * inv; ov.y = o[i*4+1] * inv;
        ov.z = o[i*4+2] * inv; ov.w = o[i*4+3] * inv;
        dst[i] = ov;
    }
}

// -------------------- launch ---------------------------------------------------
extern "C" void kernel_launch(void* const* d_in, const int* in_sizes, int n_in,
                              void* d_out, int out_size) {
    const float* in  = (const float*)d_in[0];
    const float* Wq  = (const float*)d_in[1];
    const float* bq  = (const float*)d_in[2];
    const float* Wk  = (const float*)d_in[3];
    const float* bk  = (const float*)d_in[4];
    const float* Wv  = (const float*)d_in[5];
    const float* bv  = (const float*)d_in[6];
    const float* Wo  = (const float*)d_in[7];
    const float* bo  = (const float*)d_in[8];
    const float* W1  = (const float*)d_in[9];
    const float* b1  = (const float*)d_in[10];
    const float* W2  = (const float*)d_in[11];
    const float* b2  = (const float*)d_in[12];
    const float* lng = (const float*)d_in[13];
    const float* lnb = (const float*)d_in[14];
    float* out = (float*)d_out;

    float *h, *hn, *q, *k, *v, *ctx, *tmp, *pe;
    cudaGetSymbolAddress((void**)&h,   g_h);
    cudaGetSymbolAddress((void**)&hn,  g_hn);
    cudaGetSymbolAddress((void**)&q,   g_q);
    cudaGetSymbolAddress((void**)&k,   g_k);
    cudaGetSymbolAddress((void**)&v,   g_v);
    cudaGetSymbolAddress((void**)&ctx, g_ctx);
    cudaGetSymbolAddress((void**)&tmp, g_tmp);
    cudaGetSymbolAddress((void**)&pe,  g_pe);

    pe_kernel<<<128, 256>>>(pe);
    addpos_kernel<<<(ROWS * DD / 4) / 256, 256>>>(in, pe, h);

    for (int i = 0; i < NB; i++) {
        const float* Wqi = Wq + i * DD * DD; const float* bqi = bq + i * DD;
        const float* Wki = Wk + i * DD * DD; const float* bki = bk + i * DD;
        const float* Wvi = Wv + i * DD * DD; const float* bvi = bv + i * DD;
        const float* Woi = Wo + i * DD * DD; const float* boi = bo + i * DD;
        const float* W1i = W1 + i * DD * DD; const float* b1i = b1 + i * DD;
        const float* W2i = W2 + i * DD * DD; const float* b2i = b2 + i * DD;

        ln_kernel<<<ROWS / 8, 256>>>(h, lng + (2 * i) * DD, lnb + (2 * i) * DD, hn);
        gemm128_kernel<3><<<ROWS / 64, 256>>>(hn, Wqi, bqi, nullptr, q);
        gemm128_kernel<3><<<ROWS / 64, 256>>>(hn, Wki, bki, nullptr, k);
        gemm128_kernel<3><<<ROWS / 64, 256>>>(hn, Wvi, bvi, nullptr, v);
        attn_kernel<<<BB * HH * (TT / 128), 128>>>(q, k, v, ctx);
        gemm128_kernel<0><<<ROWS / 64, 256>>>(ctx, Woi, boi, nullptr, h);
        ln_kernel<<<ROWS / 8, 256>>>(h, lng + (2 * i + 1) * DD, lnb + (2 * i + 1) * DD, hn);
        gemm128_kernel<1><<<ROWS / 64, 256>>>(hn, W1i, b1i, nullptr, tmp);
        gemm128_kernel<2><<<ROWS / 64, 256>>>(tmp, W2i, b2i, hn, h);
    }
    ln_kernel<<<ROWS / 8, 256>>>(h, lng + 3 * DD, lnb + 3 * DD, out);
}

// round 2
// speedup vs baseline: 1.3345x; 1.3345x over previous
#include <cuda_runtime.h>
#include <math.h>

#define NB 2
#define BB 4
#define TT 2048
#define DD 128
#define HH 4
#define DK 32
#define ROWS (BB*TT)          // 8192
#define LN_EPS 1e-3f

#define NBAR(id, n) asm volatile("bar.sync %0, %1;" :: "r"(id), "r"(n) : "memory")

// -------------------- scratch (device globals; no allocs allowed) ------------
__device__ float g_h  [ROWS*DD];
__device__ float g_hn [ROWS*DD];
__device__ float g_q  [ROWS*DD];
__device__ float g_k  [ROWS*DD];
__device__ float g_v  [ROWS*DD];
__device__ float g_ctx[ROWS*DD];
__device__ float g_tmp[ROWS*DD];
__device__ float g_pe [TT*DD];

// -------------------- positional encoding -------------------------------------
// angle in fp64 (exact vs numpy), range-reduce in fp64, evaluate sin/cos in fp32.
__global__ void pe_kernel(float* __restrict__ pe) {
    int i = blockIdx.x;  // feature 0..127
    double f = exp(-((double)(2 * i) / 128.0) * 9.210340371976184);  // 10000^(-2i/128)
    const double TWO_PI = 6.283185307179586;
    const double INV_TWO_PI = 0.15915494309189535;
    for (int t = threadIdx.x; t < TT; t += blockDim.x) {
        double ang = (double)t * f;
        double r = ang - TWO_PI * floor(ang * INV_TWO_PI);
        float rf = (float)r;
        pe[t * DD + i] = (i & 1) ? cosf(rf) : sinf(rf);
    }
}

// -------------------- h = inputs + pe ----------------------------------------
__global__ void addpos_kernel(const float* __restrict__ in, const float* __restrict__ pe,
                              float* __restrict__ h) {
    int gi = blockIdx.x * blockDim.x + threadIdx.x;
    const float4* in4 = (const float4*)in;
    const float4* pe4 = (const float4*)pe;
    float4 a = in4[gi];
    float4 p = pe4[gi & ((TT * DD / 4) - 1)];
    a.x += p.x; a.y += p.y; a.z += p.z; a.w += p.w;
    ((float4*)h)[gi] = a;
}

// -------------------- LayerNorm: one warp per 128-wide row --------------------
__global__ void ln_kernel(const float* __restrict__ x, const float* __restrict__ g,
                          const float* __restrict__ b, float* __restrict__ y) {
    int row  = blockIdx.x * 8 + (threadIdx.x >> 5);
    int lane = threadIdx.x & 31;
    float4 xv = ((const float4*)x)[row * 32 + lane];
    float s = xv.x + xv.y + xv.z + xv.w;
    #pragma unroll
    for (int o = 16; o > 0; o >>= 1) s += __shfl_xor_sync(0xffffffff, s, o);
    float mu = s * (1.0f / 128.0f);
    float dx0 = xv.x - mu, dx1 = xv.y - mu, dx2 = xv.z - mu, dx3 = xv.w - mu;
    float sq = dx0*dx0 + dx1*dx1 + dx2*dx2 + dx3*dx3;
    #pragma unroll
    for (int o = 16; o > 0; o >>= 1) sq += __shfl_xor_sync(0xffffffff, sq, o);
    float var = sq * (1.0f / 128.0f);
    float r = rsqrtf(var + LN_EPS);
    float4 gv = ((const float4*)g)[lane];
    float4 bv = ((const float4*)b)[lane];
    float4 ov;
    ov.x = gv.x * dx0 * r + bv.x;
    ov.y = gv.y * dx1 * r + bv.y;
    ov.z = gv.z * dx2 * r + bv.z;
    ov.w = gv.w * dx3 * r + bv.w;
    ((float4*)y)[row * 32 + lane] = ov;
}

// -------------------- GEMM C[8192,128] = A[8192,128] @ W[128,128] + bias -----
// M-tile = 32 -> grid 256 (fills all 148 SMs, 2+ blocks/SM).
// MODE: 0 plain, 1 relu, 2 +residual R, 3 scatter to [B,H,T,DK]
template <int MODE>
__global__ __launch_bounds__(256) void gemm128_kernel(
        const float* __restrict__ A, const float* __restrict__ W,
        const float* __restrict__ bias, const float* __restrict__ R,
        float* __restrict__ C) {
    __shared__ float As[32][33];
    __shared__ float Ws[32][128];
    int tid = threadIdx.x;
    int tx = tid & 31;      // -> N/4
    int ty = tid >> 5;      // -> M group (0..7)
    int m0 = blockIdx.x * 32;
    float acc[4][4] = {};

    for (int k0 = 0; k0 < 128; k0 += 32) {
        {   // A tile: 32x32 = 256 float4, one per thread
            int m = tid >> 3, kv = tid & 7;
            float4 av = *(const float4*)&A[(m0 + m) * 128 + k0 + kv * 4];
            As[m][kv*4+0] = av.x; As[m][kv*4+1] = av.y;
            As[m][kv*4+2] = av.z; As[m][kv*4+3] = av.w;
        }
        #pragma unroll
        for (int l = 0; l < 4; l++) {   // W tile: 32x128 = 1024 float4
            int e = tid + l * 256;
            int kk = e >> 5, nv = e & 31;
            *(float4*)&Ws[kk][nv * 4] = *(const float4*)&W[(k0 + kk) * 128 + nv * 4];
        }
        __syncthreads();
        #pragma unroll
        for (int kk = 0; kk < 32; kk++) {
            float4 wv = *(const float4*)&Ws[kk][tx * 4];
            #pragma unroll
            for (int r = 0; r < 4; r++) {
                float a = As[ty * 4 + r][kk];
                acc[r][0] += a * wv.x; acc[r][1] += a * wv.y;
                acc[r][2] += a * wv.z; acc[r][3] += a * wv.w;
            }
        }
        __syncthreads();
    }

    int n = tx * 4;
    float4 bv = *(const float4*)&bias[n];
    #pragma unroll
    for (int r = 0; r < 4; r++) {
        int m = m0 + ty * 4 + r;
        float4 o;
        o.x = acc[r][0] + bv.x; o.y = acc[r][1] + bv.y;
        o.z = acc[r][2] + bv.z; o.w = acc[r][3] + bv.w;
        if (MODE == 1) {
            o.x = fmaxf(o.x, 0.f); o.y = fmaxf(o.y, 0.f);
            o.z = fmaxf(o.z, 0.f); o.w = fmaxf(o.w, 0.f);
        }
        if (MODE == 2) {
            float4 rv = *(const float4*)&R[m * 128 + n];
            o.x += rv.x; o.y += rv.y; o.z += rv.z; o.w += rv.w;
        }
        if (MODE == 3) {
            int b = m >> 11, t = m & 2047, hh = n >> 5, dk = n & 31;
            *(float4*)&C[(((b << 2) + hh) * 2048 + t) * 32 + dk] = o;
        } else {
            *(float4*)&C[m * 128 + n] = o;
        }
    }
}

// -------------------- flash attention v2 --------------------------------------
// 256 blocks (16 bh x 16 q-chunks of 128), 256 threads:
//   threads [0,128)  = half 0 -> keys [0,1024)
//   threads [128,256)= half 1 -> keys [1024,2048)
// each thread owns one query for its key range; partials merged via smem.
// K/V tiles of 64 keys per half, per-half named barriers.
__global__ __launch_bounds__(256) void attn_kernel(
        const float* __restrict__ Q, const float* __restrict__ K,
        const float* __restrict__ V, float* __restrict__ ctx) {
    __shared__ float smem[8192];   // 32KB: Ks[2][2048] @0, Vs[2][2048] @4096
    int bid = blockIdx.x;          // 0..255
    int bh  = bid >> 4;            // 0..15
    int qc  = bid & 15;
    int tid = threadIdx.x;
    int half = tid >> 7;           // 0/1
    int lt   = tid & 127;
    int barid = half + 1;

    float* Ks = smem + half * 2048;
    float* Vs = smem + 4096 + half * 2048;

    const float scale = 0.17677669529663687f;  // 1/sqrt(32)
    int qi = qc * 128 + lt;
    float qr[32];
    {
        const float4* q4 = (const float4*)(Q + (size_t)(bh * TT + qi) * 32);
        #pragma unroll
        for (int i = 0; i < 8; i++) {
            float4 t = q4[i];
            qr[i*4+0] = t.x * scale; qr[i*4+1] = t.y * scale;
            qr[i*4+2] = t.z * scale; qr[i*4+3] = t.w * scale;
        }
    }
    float m = -1e30f, l = 0.f;
    float o[32];
    #pragma unroll
    for (int d = 0; d < 32; d++) o[d] = 0.f;

    const float4* Kb = (const float4*)(K + (size_t)(bh * TT + half * 1024) * 32);
    const float4* Vb = (const float4*)(V + (size_t)(bh * TT + half * 1024) * 32);
    float4* kd = (float4*)Ks;
    float4* vd = (float4*)Vs;

    for (int t0 = 0; t0 < 1024; t0 += 64) {
        int base = t0 * 8;         // float4s per 64-key tile = 512
        #pragma unroll
        for (int i = 0; i < 4; i++) {
            kd[lt + i * 128] = Kb[base + lt + i * 128];
            vd[lt + i * 128] = Vb[base + lt + i * 128];
        }
        NBAR(barid, 128);
        for (int j = 0; j < 64; j++) {
            const float* kj = Ks + j * 32;
            float s = 0.f;
            #pragma unroll
            for (int d = 0; d < 32; d++) s += qr[d] * kj[d];
            float mn = fmaxf(m, s);
            if (mn > m) {
                float c = __expf(m - mn);
                l *= c;
                #pragma unroll
                for (int d = 0; d < 32; d++) o[d] *= c;
                m = mn;
            }
            float p = __expf(s - m);
            l += p;
            const float* vj = Vs + j * 32;
            #pragma unroll
            for (int d = 0; d < 32; d++) o[d] += p * vj[d];
        }
        NBAR(barid, 128);
    }

    __syncthreads();               // everyone done with tiles
    if (half == 1) {               // store partials (transposed -> conflict-free)
        smem[lt] = m;
        smem[128 + lt] = l;
        #pragma unroll
        for (int d = 0; d < 32; d++) smem[256 + d * 128 + lt] = o[d];
    }
    __syncthreads();
    if (half == 0) {
        float m1 = smem[lt], l1 = smem[128 + lt];
        float mn = fmaxf(m, m1);
        float c0 = __expf(m - mn), c1 = __expf(m1 - mn);
        float inv = 1.0f / (l * c0 + l1 * c1);
        int b = bh >> 2, hh = bh & 3;
        float4* dst = (float4*)(ctx + (size_t)(b * TT + qi) * 128 + hh * 32);
        #pragma unroll
        for (int i = 0; i < 8; i++) {
            float4 ov;
            ov.x = (o[i*4+0]*c0 + smem[256 + (i*4+0)*128 + lt]*c1) * inv;
            ov.y = (o[i*4+1]*c0 + smem[256 + (i*4+1)*128 + lt]*c1) * inv;
            ov.z = (o[i*4+2]*c0 + smem[256 + (i*4+2)*128 + lt]*c1) * inv;
            ov.w = (o[i*4+3]*c0 + smem[256 + (i*4+3)*128 + lt]*c1) * inv;
            dst[i] = ov;
        }
    }
}

// -------------------- launch ---------------------------------------------------
extern "C" void kernel_launch(void* const* d_in, const int* in_sizes, int n_in,
                              void* d_out, int out_size) {
    const float* in  = (const float*)d_in[0];
    const float* Wq  = (const float*)d_in[1];
    const float* bq  = (const float*)d_in[2];
    const float* Wk  = (const float*)d_in[3];
    const float* bk  = (const float*)d_in[4];
    const float* Wv  = (const float*)d_in[5];
    const float* bv  = (const float*)d_in[6];
    const float* Wo  = (const float*)d_in[7];
    const float* bo  = (const float*)d_in[8];
    const float* W1  = (const float*)d_in[9];
    const float* b1  = (const float*)d_in[10];
    const float* W2  = (const float*)d_in[11];
    const float* b2  = (const float*)d_in[12];
    const float* lng = (const float*)d_in[13];
    const float* lnb = (const float*)d_in[14];
    float* out = (float*)d_out;

    float *h, *hn, *q, *k, *v, *ctx, *tmp, *pe;
    cudaGetSymbolAddress((void**)&h,   g_h);
    cudaGetSymbolAddress((void**)&hn,  g_hn);
    cudaGetSymbolAddress((void**)&q,   g_q);
    cudaGetSymbolAddress((void**)&k,   g_k);
    cudaGetSymbolAddress((void**)&v,   g_v);
    cudaGetSymbolAddress((void**)&ctx, g_ctx);
    cudaGetSymbolAddress((void**)&tmp, g_tmp);
    cudaGetSymbolAddress((void**)&pe,  g_pe);

    pe_kernel<<<128, 256>>>(pe);
    addpos_kernel<<<(ROWS * DD / 4) / 256, 256>>>(in, pe, h);

    for (int i = 0; i < NB; i++) {
        const float* Wqi = Wq + i * DD * DD; const float* bqi = bq + i * DD;
        const float* Wki = Wk + i * DD * DD; const float* bki = bk + i * DD;
        const float* Wvi = Wv + i * DD * DD; const float* bvi = bv + i * DD;
        const float* Woi = Wo + i * DD * DD; const float* boi = bo + i * DD;
        const float* W1i = W1 + i * DD * DD; const float* b1i = b1 + i * DD;
        const float* W2i = W2 + i * DD * DD; const float* b2i = b2 + i * DD;

        ln_kernel<<<ROWS / 8, 256>>>(h, lng + (2 * i) * DD, lnb + (2 * i) * DD, hn);
        gemm128_kernel<3><<<ROWS / 32, 256>>>(hn, Wqi, bqi, nullptr, q);
        gemm128_kernel<3><<<ROWS / 32, 256>>>(hn, Wki, bki, nullptr, k);
        gemm128_kernel<3><<<ROWS / 32, 256>>>(hn, Wvi, bvi, nullptr, v);
        attn_kernel<<<256, 256>>>(q, k, v, ctx);
        gemm128_kernel<0><<<ROWS / 32, 256>>>(ctx, Woi, boi, nullptr, h);
        ln_kernel<<<ROWS / 8, 256>>>(h, lng + (2 * i + 1) * DD, lnb + (2 * i + 1) * DD, hn);
        gemm128_kernel<1><<<ROWS / 32, 256>>>(hn, W1i, b1i, nullptr, tmp);
        gemm128_kernel<2><<<ROWS / 32, 256>>>(tmp, W2i, b2i, hn, h);
    }
    ln_kernel<<<ROWS / 8, 256>>>(h, lng + 3 * DD, lnb + 3 * DD, out);
}

// round 4
// speedup vs baseline: 1.8181x; 1.3624x over previous
#include <cuda_runtime.h>
#include <cuda_bf16.h>
#include <stdint.h>
#include <math.h>

#define NB 2
#define BB 4
#define TT 2048
#define DD 128
#define HH 4
#define DK 32
#define ROWS (BB*TT)          // 8192
#define LN_EPS 1e-3f

// -------------------- scratch (device globals; no allocs allowed) ------------
__device__ float g_h  [ROWS*DD];
__device__ float g_hn [ROWS*DD];
__device__ float g_q  [ROWS*DD];
__device__ float g_k  [ROWS*DD];
__device__ float g_v  [ROWS*DD];
__device__ float g_ctx[ROWS*DD];
__device__ float g_tmp[ROWS*DD];
__device__ float g_pe [TT*DD];

// -------------------- positional encoding -------------------------------------
__global__ void pe_kernel(float* __restrict__ pe) {
    int i = blockIdx.x;  // feature 0..127
    double f = exp(-((double)(2 * i) / 128.0) * 9.210340371976184);  // 10000^(-2i/128)
    const double TWO_PI = 6.283185307179586;
    const double INV_TWO_PI = 0.15915494309189535;
    for (int t = threadIdx.x; t < TT; t += blockDim.x) {
        double ang = (double)t * f;
        double r = ang - TWO_PI * floor(ang * INV_TWO_PI);
        float rf = (float)r;
        pe[t * DD + i] = (i & 1) ? cosf(rf) : sinf(rf);
    }
}

// -------------------- h = inputs + pe ----------------------------------------
__global__ void addpos_kernel(const float* __restrict__ in, const float* __restrict__ pe,
                              float* __restrict__ h) {
    int gi = blockIdx.x * blockDim.x + threadIdx.x;
    const float4* in4 = (const float4*)in;
    const float4* pe4 = (const float4*)pe;
    float4 a = in4[gi];
    float4 p = pe4[gi & ((TT * DD / 4) - 1)];
    a.x += p.x; a.y += p.y; a.z += p.z; a.w += p.w;
    ((float4*)h)[gi] = a;
}

// -------------------- LayerNorm: one warp per 128-wide row --------------------
__global__ void ln_kernel(const float* __restrict__ x, const float* __restrict__ g,
                          const float* __restrict__ b, float* __restrict__ y) {
    int row  = blockIdx.x * 8 + (threadIdx.x >> 5);
    int lane = threadIdx.x & 31;
    float4 xv = ((const float4*)x)[row * 32 + lane];
    float s = xv.x + xv.y + xv.z + xv.w;
    #pragma unroll
    for (int o = 16; o > 0; o >>= 1) s += __shfl_xor_sync(0xffffffff, s, o);
    float mu = s * (1.0f / 128.0f);
    float dx0 = xv.x - mu, dx1 = xv.y - mu, dx2 = xv.z - mu, dx3 = xv.w - mu;
    float sq = dx0*dx0 + dx1*dx1 + dx2*dx2 + dx3*dx3;
    #pragma unroll
    for (int o = 16; o > 0; o >>= 1) sq += __shfl_xor_sync(0xffffffff, sq, o);
    float var = sq * (1.0f / 128.0f);
    float r = rsqrtf(var + LN_EPS);
    float4 gv = ((const float4*)g)[lane];
    float4 bv = ((const float4*)b)[lane];
    float4 ov;
    ov.x = gv.x * dx0 * r + bv.x;
    ov.y = gv.y * dx1 * r + bv.y;
    ov.z = gv.z * dx2 * r + bv.z;
    ov.w = gv.w * dx3 * r + bv.w;
    ((float4*)y)[row * 32 + lane] = ov;
}

// -------------------- GEMM C[8192,128] = A[8192,128] @ W[128,128] + bias -----
template <int MODE>
__global__ __launch_bounds__(256) void gemm128_kernel(
        const float* __restrict__ A, const float* __restrict__ W,
        const float* __restrict__ bias, const float* __restrict__ R,
        float* __restrict__ C) {
    __shared__ float As[32][33];
    __shared__ float Ws[32][128];
    int tid = threadIdx.x;
    int tx = tid & 31;
    int ty = tid >> 5;
    int m0 = blockIdx.x * 32;
    float acc[4][4] = {};

    for (int k0 = 0; k0 < 128; k0 += 32) {
        {
            int m = tid >> 3, kv = tid & 7;
            float4 av = *(const float4*)&A[(m0 + m) * 128 + k0 + kv * 4];
            As[m][kv*4+0] = av.x; As[m][kv*4+1] = av.y;
            As[m][kv*4+2] = av.z; As[m][kv*4+3] = av.w;
        }
        #pragma unroll
        for (int l = 0; l < 4; l++) {
            int e = tid + l * 256;
            int kk = e >> 5, nv = e & 31;
            *(float4*)&Ws[kk][nv * 4] = *(const float4*)&W[(k0 + kk) * 128 + nv * 4];
        }
        __syncthreads();
        #pragma unroll
        for (int kk = 0; kk < 32; kk++) {
            float4 wv = *(const float4*)&Ws[kk][tx * 4];
            #pragma unroll
            for (int r = 0; r < 4; r++) {
                float a = As[ty * 4 + r][kk];
                acc[r][0] += a * wv.x; acc[r][1] += a * wv.y;
                acc[r][2] += a * wv.z; acc[r][3] += a * wv.w;
            }
        }
        __syncthreads();
    }

    int n = tx * 4;
    float4 bv = *(const float4*)&bias[n];
    #pragma unroll
    for (int r = 0; r < 4; r++) {
        int m = m0 + ty * 4 + r;
        float4 o;
        o.x = acc[r][0] + bv.x; o.y = acc[r][1] + bv.y;
        o.z = acc[r][2] + bv.z; o.w = acc[r][3] + bv.w;
        if (MODE == 1) {
            o.x = fmaxf(o.x, 0.f); o.y = fmaxf(o.y, 0.f);
            o.z = fmaxf(o.z, 0.f); o.w = fmaxf(o.w, 0.f);
        }
        if (MODE == 2) {
            float4 rv = *(const float4*)&R[m * 128 + n];
            o.x += rv.x; o.y += rv.y; o.z += rv.z; o.w += rv.w;
        }
        if (MODE == 3) {
            int b = m >> 11, t = m & 2047, hh = n >> 5, dk = n & 31;
            *(float4*)&C[(((b << 2) + hh) * 2048 + t) * 32 + dk] = o;
        } else {
            *(float4*)&C[m * 128 + n] = o;
        }
    }
}

// -------------------- split-bf16 helpers ---------------------------------------
__device__ __forceinline__ uint32_t pk_bf2(float a, float b) {
    __nv_bfloat162 t = __floats2bfloat162_rn(a, b);
    return *reinterpret_cast<uint32_t*>(&t);
}
__device__ __forceinline__ void split2(float a, float b, uint32_t& h, uint32_t& l) {
    float ah = __bfloat162float(__float2bfloat16(a));
    float bh = __bfloat162float(__float2bfloat16(b));
    h = pk_bf2(ah, bh);
    l = pk_bf2(a - ah, b - bh);
}
__device__ __forceinline__ void mma16816(float c[4], const uint32_t a[4], const uint32_t b[2]) {
    asm volatile(
        "mma.sync.aligned.m16n8k16.row.col.f32.bf16.bf16.f32 "
        "{%0,%1,%2,%3}, {%4,%5,%6,%7}, {%8,%9}, {%0,%1,%2,%3};\n"
        : "+f"(c[0]), "+f"(c[1]), "+f"(c[2]), "+f"(c[3])
        : "r"(a[0]), "r"(a[1]), "r"(a[2]), "r"(a[3]), "r"(b[0]), "r"(b[1]));
}

// -------------------- flash attention, split-bf16 mma.sync ---------------------
// grid 512 = 16 bh x 32 q-chunks(64); 4 warps, 16 q-rows per warp.
// smem per 64-key tile: K split (key-major, d bf16x2 pairs), V^T split (d-major,
// key bf16x2 pairs). Register-staged prefetch of next tile.
__global__ __launch_bounds__(128) void attn_kernel(
        const float* __restrict__ Q, const float* __restrict__ K,
        const float* __restrict__ V, float* __restrict__ ctx) {
    __shared__ uint32_t Ksh[64 * 17];
    __shared__ uint32_t Ksl[64 * 17];
    __shared__ uint32_t Vth[32 * 33];
    __shared__ uint32_t Vtl[32 * 33];

    int bid = blockIdx.x;
    int bh  = bid >> 5;            // 0..15
    int qc  = bid & 31;            // 0..31
    int q0  = qc * 64;
    int tid = threadIdx.x;
    int w    = tid >> 5;
    int lane = tid & 31;
    int lq   = lane >> 2;          // 0..7
    int lr   = lane & 3;           // 0..3

    const float* Qg = Q + (size_t)bh * TT * 32;
    const float* Kg = K + (size_t)bh * TT * 32;
    const float* Vg = V + (size_t)bh * TT * 32;

    const float scale = 0.17677669529663687f;  // 1/sqrt(32)
    int row0 = q0 + w * 16 + lq;

    // Q fragments (A, m16n16), pre-scaled, split hi/lo. chunks c2: d in [16c2,16c2+16)
    uint32_t qh[2][4], ql[2][4];
    #pragma unroll
    for (int c2 = 0; c2 < 2; c2++) {
        #pragma unroll
        for (int r = 0; r < 4; r++) {
            int rr = row0 + ((r & 1) ? 8 : 0);
            int d  = c2 * 16 + 2 * lr + ((r >= 2) ? 8 : 0);
            float2 qv = *(const float2*)&Qg[(size_t)rr * 32 + d];
            split2(qv.x * scale, qv.y * scale, qh[c2][r], ql[c2][r]);
        }
    }

    float m0 = -1e30f, m1 = -1e30f, l0 = 0.f, l1 = 0.f;
    float o[4][4] = {};

    // ---- staging registers for next tile ----
    float4 kr[4];
    float2 vr0[4], vr1[4];
    int vj  = tid & 31;            // key-pair index 0..31
    int vd0 = ((tid >> 5) << 1);   // base even d (add pass*8)
    {
        int t0 = 0;
        #pragma unroll
        for (int p = 0; p < 4; p++) {
            int e = tid + p * 128;
            kr[p] = *(const float4*)&Kg[(size_t)(t0 + (e >> 3)) * 32 + (e & 7) * 4];
        }
        #pragma unroll
        for (int p = 0; p < 4; p++) {
            int d0 = vd0 + p * 8;
            vr0[p] = *(const float2*)&Vg[(size_t)(t0 + 2 * vj) * 32 + d0];
            vr1[p] = *(const float2*)&Vg[(size_t)(t0 + 2 * vj + 1) * 32 + d0];
        }
    }

    for (int tile = 0; tile < 32; tile++) {
        // ---- store staged tile to smem (convert + split) ----
        #pragma unroll
        for (int p = 0; p < 4; p++) {
            int e = tid + p * 128;
            int key = e >> 3, dq = e & 7;
            uint32_t h0, lo0, h1, lo1;
            split2(kr[p].x, kr[p].y, h0, lo0);
            split2(kr[p].z, kr[p].w, h1, lo1);
            Ksh[key * 17 + 2 * dq]     = h0;
            Ksh[key * 17 + 2 * dq + 1] = h1;
            Ksl[key * 17 + 2 * dq]     = lo0;
            Ksl[key * 17 + 2 * dq + 1] = lo1;
        }
        #pragma unroll
        for (int p = 0; p < 4; p++) {
            int d0 = vd0 + p * 8;
            float ax = __bfloat162float(__float2bfloat16(vr0[p].x));
            float bx = __bfloat162float(__float2bfloat16(vr1[p].x));
            float ay = __bfloat162float(__float2bfloat16(vr0[p].y));
            float by = __bfloat162float(__float2bfloat16(vr1[p].y));
            Vth[d0 * 33 + vj]       = pk_bf2(ax, bx);
            Vth[(d0 + 1) * 33 + vj] = pk_bf2(ay, by);
            Vtl[d0 * 33 + vj]       = pk_bf2(vr0[p].x - ax, vr1[p].x - bx);
            Vtl[(d0 + 1) * 33 + vj] = pk_bf2(vr0[p].y - ay, vr1[p].y - by);
        }
        __syncthreads();

        // ---- prefetch next tile into regs ----
        if (tile < 31) {
            int t0 = (tile + 1) * 64;
            #pragma unroll
            for (int p = 0; p < 4; p++) {
                int e = tid + p * 128;
                kr[p] = *(const float4*)&Kg[(size_t)(t0 + (e >> 3)) * 32 + (e & 7) * 4];
            }
            #pragma unroll
            for (int p = 0; p < 4; p++) {
                int d0 = vd0 + p * 8;
                vr0[p] = *(const float2*)&Vg[(size_t)(t0 + 2 * vj) * 32 + d0];
                vr1[p] = *(const float2*)&Vg[(size_t)(t0 + 2 * vj + 1) * 32 + d0];
            }
        }

        // ---- QK^T: scores c[8][4] over 64 keys ----
        float c[8][4] = {};
        #pragma unroll
        for (int nt = 0; nt < 8; nt++) {
            int key = nt * 8 + lq;
            const uint32_t* kh = &Ksh[key * 17 + lr];
            const uint32_t* kl = &Ksl[key * 17 + lr];
            #pragma unroll
            for (int kc = 0; kc < 2; kc++) {
                uint32_t bhf[2] = { kh[8 * kc], kh[8 * kc + 4] };
                uint32_t blf[2] = { kl[8 * kc], kl[8 * kc + 4] };
                mma16816(c[nt], qh[kc], bhf);
                mma16816(c[nt], qh[kc], blf);
                mma16816(c[nt], ql[kc], bhf);
            }
        }

        // ---- online softmax ----
        float mx0 = -1e30f, mx1 = -1e30f;
        #pragma unroll
        for (int nt = 0; nt < 8; nt++) {
            mx0 = fmaxf(mx0, fmaxf(c[nt][0], c[nt][1]));
            mx1 = fmaxf(mx1, fmaxf(c[nt][2], c[nt][3]));
        }
        mx0 = fmaxf(mx0, __shfl_xor_sync(0xffffffff, mx0, 1));
        mx0 = fmaxf(mx0, __shfl_xor_sync(0xffffffff, mx0, 2));
        mx1 = fmaxf(mx1, __shfl_xor_sync(0xffffffff, mx1, 1));
        mx1 = fmaxf(mx1, __shfl_xor_sync(0xffffffff, mx1, 2));
        float nm0 = fmaxf(m0, mx0), nm1 = fmaxf(m1, mx1);
        float f0 = __expf(m0 - nm0), f1 = __expf(m1 - nm1);
        m0 = nm0; m1 = nm1;
        l0 *= f0; l1 *= f1;
        #pragma unroll
        for (int dt = 0; dt < 4; dt++) {
            o[dt][0] *= f0; o[dt][1] *= f0;
            o[dt][2] *= f1; o[dt][3] *= f1;
        }
        #pragma unroll
        for (int nt = 0; nt < 8; nt++) {
            c[nt][0] = __expf(c[nt][0] - m0);
            c[nt][1] = __expf(c[nt][1] - m0);
            c[nt][2] = __expf(c[nt][2] - m1);
            c[nt][3] = __expf(c[nt][3] - m1);
            l0 += c[nt][0] + c[nt][1];
            l1 += c[nt][2] + c[nt][3];
        }

        // ---- P @ V ----
        #pragma unroll
        for (int kc = 0; kc < 4; kc++) {
            uint32_t ah[4], al[4];
            split2(c[2*kc][0],   c[2*kc][1],   ah[0], al[0]);
            split2(c[2*kc][2],   c[2*kc][3],   ah[1], al[1]);
            split2(c[2*kc+1][0], c[2*kc+1][1], ah[2], al[2]);
            split2(c[2*kc+1][2], c[2*kc+1][3], ah[3], al[3]);
            #pragma unroll
            for (int dt = 0; dt < 4; dt++) {
                int d = dt * 8 + lq;
                const uint32_t* vh = &Vth[d * 33 + kc * 8 + lr];
                const uint32_t* vl = &Vtl[d * 33 + kc * 8 + lr];
                uint32_t bhf[2] = { vh[0], vh[4] };
                uint32_t blf[2] = { vl[0], vl[4] };
                mma16816(o[dt], ah, bhf);
                mma16816(o[dt], ah, blf);
                mma16816(o[dt], al, bhf);
            }
        }
        __syncthreads();
    }

    // ---- epilogue ----
    l0 += __shfl_xor_sync(0xffffffff, l0, 1);
    l0 += __shfl_xor_sync(0xffffffff, l0, 2);
    l1 += __shfl_xor_sync(0xffffffff, l1, 1);
    l1 += __shfl_xor_sync(0xffffffff, l1, 2);
    float inv0 = 1.0f / l0, inv1 = 1.0f / l1;
    int b = bh >> 2, hh = bh & 3;
    #pragma unroll
    for (int dt = 0; dt < 4; dt++) {
        int d = dt * 8 + 2 * lr;
        float2 v0 = { o[dt][0] * inv0, o[dt][1] * inv0 };
        float2 v1 = { o[dt][2] * inv1, o[dt][3] * inv1 };
        *(float2*)&ctx[(size_t)(b * TT + row0) * 128 + hh * 32 + d]       = v0;
        *(float2*)&ctx[(size_t)(b * TT + row0 + 8) * 128 + hh * 32 + d]   = v1;
    }
}

// -------------------- launch ---------------------------------------------------
extern "C" void kernel_launch(void* const* d_in, const int* in_sizes, int n_in,
                              void* d_out, int out_size) {
    const float* in  = (const float*)d_in[0];
    const float* Wq  = (const float*)d_in[1];
    const float* bq  = (const float*)d_in[2];
    const float* Wk  = (const float*)d_in[3];
    const float* bk  = (const float*)d_in[4];
    const float* Wv  = (const float*)d_in[5];
    const float* bv  = (const float*)d_in[6];
    const float* Wo  = (const float*)d_in[7];
    const float* bo  = (const float*)d_in[8];
    const float* W1  = (const float*)d_in[9];
    const float* b1  = (const float*)d_in[10];
    const float* W2  = (const float*)d_in[11];
    const float* b2  = (const float*)d_in[12];
    const float* lng = (const float*)d_in[13];
    const float* lnb = (const float*)d_in[14];
    float* out = (float*)d_out;

    float *h, *hn, *q, *k, *v, *ctx, *tmp, *pe;
    cudaGetSymbolAddress((void**)&h,   g_h);
    cudaGetSymbolAddress((void**)&hn,  g_hn);
    cudaGetSymbolAddress((void**)&q,   g_q);
    cudaGetSymbolAddress((void**)&k,   g_k);
    cudaGetSymbolAddress((void**)&v,   g_v);
    cudaGetSymbolAddress((void**)&ctx, g_ctx);
    cudaGetSymbolAddress((void**)&tmp, g_tmp);
    cudaGetSymbolAddress((void**)&pe,  g_pe);

    pe_kernel<<<128, 256>>>(pe);
    addpos_kernel<<<(ROWS * DD / 4) / 256, 256>>>(in, pe, h);

    for (int i = 0; i < NB; i++) {
        const float* Wqi = Wq + i * DD * DD; const float* bqi = bq + i * DD;
        const float* Wki = Wk + i * DD * DD; const float* bki = bk + i * DD;
        const float* Wvi = Wv + i * DD * DD; const float* bvi = bv + i * DD;
        const float* Woi = Wo + i * DD * DD; const float* boi = bo + i * DD;
        const float* W1i = W1 + i * DD * DD; const float* b1i = b1 + i * DD;
        const float* W2i = W2 + i * DD * DD; const float* b2i = b2 + i * DD;

        ln_kernel<<<ROWS / 8, 256>>>(h, lng + (2 * i) * DD, lnb + (2 * i) * DD, hn);
        gemm128_kernel<3><<<ROWS / 32, 256>>>(hn, Wqi, bqi, nullptr, q);
        gemm128_kernel<3><<<ROWS / 32, 256>>>(hn, Wki, bki, nullptr, k);
        gemm128_kernel<3><<<ROWS / 32, 256>>>(hn, Wvi, bvi, nullptr, v);
        attn_kernel<<<512, 128>>>(q, k, v, ctx);
        gemm128_kernel<0><<<ROWS / 32, 256>>>(ctx, Woi, boi, nullptr, h);
        ln_kernel<<<ROWS / 8, 256>>>(h, lng + (2 * i + 1) * DD, lnb + (2 * i + 1) * DD, hn);
        gemm128_kernel<1><<<ROWS / 32, 256>>>(hn, W1i, b1i, nullptr, tmp);
        gemm128_kernel<2><<<ROWS / 32, 256>>>(tmp, W2i, b2i, hn, h);
    }
    ln_kernel<<<ROWS / 8, 256>>>(h, lng + 3 * DD, lnb + 3 * DD, out);
}

// round 5
// speedup vs baseline: 2.5304x; 1.3918x over previous
#include <cuda_runtime.h>
#include <cuda_bf16.h>
#include <stdint.h>
#include <math.h>

#define NB 2
#define BB 4
#define TT 2048
#define DD 128
#define HH 4
#define DK 32
#define ROWS (BB*TT)          // 8192
#define LN_EPS 1e-3f

// -------------------- scratch (device globals; no allocs allowed) ------------
__device__ float g_h  [ROWS*DD];
__device__ float g_hn [ROWS*DD];
__device__ float g_q  [ROWS*DD];
__device__ float g_k  [ROWS*DD];
__device__ float g_v  [ROWS*DD];
__device__ float g_ctx[ROWS*DD];
__device__ float g_tmp[ROWS*DD];
__device__ float g_pe [TT*DD];

// -------------------- positional encoding -------------------------------------
__global__ void pe_kernel(float* __restrict__ pe) {
    int i = blockIdx.x;  // feature 0..127
    double f = exp(-((double)(2 * i) / 128.0) * 9.210340371976184);  // 10000^(-2i/128)
    const double TWO_PI = 6.283185307179586;
    const double INV_TWO_PI = 0.15915494309189535;
    for (int t = threadIdx.x; t < TT; t += blockDim.x) {
        double ang = (double)t * f;
        double r = ang - TWO_PI * floor(ang * INV_TWO_PI);
        float rf = (float)r;
        pe[t * DD + i] = (i & 1) ? cosf(rf) : sinf(rf);
    }
}

// -------------------- h = inputs + pe ----------------------------------------
__global__ void addpos_kernel(const float* __restrict__ in, const float* __restrict__ pe,
                              float* __restrict__ h) {
    int gi = blockIdx.x * blockDim.x + threadIdx.x;
    const float4* in4 = (const float4*)in;
    const float4* pe4 = (const float4*)pe;
    float4 a = in4[gi];
    float4 p = pe4[gi & ((TT * DD / 4) - 1)];
    a.x += p.x; a.y += p.y; a.z += p.z; a.w += p.w;
    ((float4*)h)[gi] = a;
}

// -------------------- LayerNorm: one warp per 128-wide row --------------------
__global__ void ln_kernel(const float* __restrict__ x, const float* __restrict__ g,
                          const float* __restrict__ b, float* __restrict__ y) {
    int row  = blockIdx.x * 8 + (threadIdx.x >> 5);
    int lane = threadIdx.x & 31;
    float4 xv = ((const float4*)x)[row * 32 + lane];
    float s = xv.x + xv.y + xv.z + xv.w;
    #pragma unroll
    for (int o = 16; o > 0; o >>= 1) s += __shfl_xor_sync(0xffffffff, s, o);
    float mu = s * (1.0f / 128.0f);
    float dx0 = xv.x - mu, dx1 = xv.y - mu, dx2 = xv.z - mu, dx3 = xv.w - mu;
    float sq = dx0*dx0 + dx1*dx1 + dx2*dx2 + dx3*dx3;
    #pragma unroll
    for (int o = 16; o > 0; o >>= 1) sq += __shfl_xor_sync(0xffffffff, sq, o);
    float var = sq * (1.0f / 128.0f);
    float r = rsqrtf(var + LN_EPS);
    float4 gv = ((const float4*)g)[lane];
    float4 bv = ((const float4*)b)[lane];
    float4 ov;
    ov.x = gv.x * dx0 * r + bv.x;
    ov.y = gv.y * dx1 * r + bv.y;
    ov.z = gv.z * dx2 * r + bv.z;
    ov.w = gv.w * dx3 * r + bv.w;
    ((float4*)y)[row * 32 + lane] = ov;
}

// -------------------- split-bf16 helpers ---------------------------------------
__device__ __forceinline__ uint32_t pk_bf2(float a, float b) {
    __nv_bfloat162 t = __floats2bfloat162_rn(a, b);
    return *reinterpret_cast<uint32_t*>(&t);
}
__device__ __forceinline__ void split2(float a, float b, uint32_t& h, uint32_t& l) {
    float ah = __bfloat162float(__float2bfloat16(a));
    float bh = __bfloat162float(__float2bfloat16(b));
    h = pk_bf2(ah, bh);
    l = pk_bf2(a - ah, b - bh);
}
__device__ __forceinline__ void mma16816(float c[4], const uint32_t a[4], const uint32_t b[2]) {
    asm volatile(
        "mma.sync.aligned.m16n8k16.row.col.f32.bf16.bf16.f32 "
        "{%0,%1,%2,%3}, {%4,%5,%6,%7}, {%8,%9}, {%0,%1,%2,%3};\n"
        : "+f"(c[0]), "+f"(c[1]), "+f"(c[2]), "+f"(c[3])
        : "r"(a[0]), "r"(a[1]), "r"(a[2]), "r"(a[3]), "r"(b[0]), "r"(b[1]));
}

// -------------------- tensor-core GEMM body ------------------------------------
// C[8192,128] = A[8192,128] @ W[128,128] + bias; tile M=64 N=64, 4 warps.
// W staged in smem as split-bf16, n-major with k-pairs (stride 68 -> conflict-free).
// MODE: 0 plain, 1 relu, 2 +residual R, 3 scatter to [B,H,T,DK]
template <int MODE>
__device__ __forceinline__ void gemm_body(
        uint32_t (*Wh)[68], uint32_t (*Wl)[68],
        const float* __restrict__ A, const float* __restrict__ W,
        const float* __restrict__ bias, const float* __restrict__ R,
        float* __restrict__ C, int m0, int n0) {
    int tid = threadIdx.x;
    int w = tid >> 5, lane = tid & 31;
    int lq = lane >> 2, lr = lane & 3;

    // stage W tile [128k x 64n] as split-bf16 (pairs along k)
    for (int kp0 = 0; kp0 < 64; kp0 += 2) {
        int kp = kp0 + (tid >> 6);
        int n  = tid & 63;
        float w0 = W[(2 * kp) * 128 + n0 + n];
        float w1 = W[(2 * kp + 1) * 128 + n0 + n];
        uint32_t hi, lo;
        split2(w0, w1, hi, lo);
        Wh[n][kp] = hi;
        Wl[n][kp] = lo;
    }

    int mrow = m0 + w * 16 + lq;
    const float* Ar0 = &A[(size_t)mrow * 128];
    const float* Ar8 = Ar0 + 8 * 128;
    float acc[8][4] = {};

    float2 af[4];
    af[0] = *(const float2*)&Ar0[2 * lr];
    af[1] = *(const float2*)&Ar8[2 * lr];
    af[2] = *(const float2*)&Ar0[2 * lr + 8];
    af[3] = *(const float2*)&Ar8[2 * lr + 8];
    __syncthreads();

    #pragma unroll
    for (int kc = 0; kc < 8; kc++) {
        uint32_t ah[4], al[4];
        #pragma unroll
        for (int r = 0; r < 4; r++) split2(af[r].x, af[r].y, ah[r], al[r]);
        float2 af2[4];
        if (kc < 7) {
            int ko = (kc + 1) * 16;
            af2[0] = *(const float2*)&Ar0[ko + 2 * lr];
            af2[1] = *(const float2*)&Ar8[ko + 2 * lr];
            af2[2] = *(const float2*)&Ar0[ko + 2 * lr + 8];
            af2[3] = *(const float2*)&Ar8[ko + 2 * lr + 8];
        }
        #pragma unroll
        for (int nt = 0; nt < 8; nt++) {
            const uint32_t* ph = &Wh[nt * 8 + lq][kc * 8 + lr];
            const uint32_t* pl = &Wl[nt * 8 + lq][kc * 8 + lr];
            uint32_t bh2[2] = { ph[0], ph[4] };
            uint32_t bl2[2] = { pl[0], pl[4] };
            mma16816(acc[nt], ah, bh2);
            mma16816(acc[nt], ah, bl2);
            mma16816(acc[nt], al, bh2);
        }
        if (kc < 7) {
            af[0] = af2[0]; af[1] = af2[1]; af[2] = af2[2]; af[3] = af2[3];
        }
    }

    #pragma unroll
    for (int nt = 0; nt < 8; nt++) {
        int n = n0 + nt * 8 + 2 * lr;
        float2 bv = *(const float2*)&bias[n];
        float2 o0 = { acc[nt][0] + bv.x, acc[nt][1] + bv.y };
        float2 o1 = { acc[nt][2] + bv.x, acc[nt][3] + bv.y };
        if (MODE == 1) {
            o0.x = fmaxf(o0.x, 0.f); o0.y = fmaxf(o0.y, 0.f);
            o1.x = fmaxf(o1.x, 0.f); o1.y = fmaxf(o1.y, 0.f);
        }
        if (MODE == 2) {
            float2 r0 = *(const float2*)&R[(size_t)mrow * 128 + n];
            float2 r1 = *(const float2*)&R[(size_t)(mrow + 8) * 128 + n];
            o0.x += r0.x; o0.y += r0.y;
            o1.x += r1.x; o1.y += r1.y;
        }
        if (MODE == 3) {
            int hh = n >> 5, dk = n & 31;
            int b0i = mrow >> 11, t0i = mrow & 2047;
            *(float2*)&C[(((b0i << 2) + hh) * 2048 + t0i) * 32 + dk] = o0;
            int b1i = (mrow + 8) >> 11, t1i = (mrow + 8) & 2047;
            *(float2*)&C[(((b1i << 2) + hh) * 2048 + t1i) * 32 + dk] = o1;
        } else {
            *(float2*)&C[(size_t)mrow * 128 + n] = o0;
            *(float2*)&C[(size_t)(mrow + 8) * 128 + n] = o1;
        }
    }
}

template <int MODE>
__global__ __launch_bounds__(128) void gemm_mma_kernel(
        const float* __restrict__ A, const float* __restrict__ W,
        const float* __restrict__ bias, const float* __restrict__ R,
        float* __restrict__ C) {
    __shared__ uint32_t Wh[64][68];
    __shared__ uint32_t Wl[64][68];
    int m0 = (blockIdx.x >> 1) * 64;
    int n0 = (blockIdx.x & 1) * 64;
    gemm_body<MODE>(Wh, Wl, A, W, bias, R, C, m0, n0);
}

// fused Q/K/V: grid (256, 3); outputs scattered to [B,H,T,DK]
__global__ __launch_bounds__(128) void qkv_mma_kernel(
        const float* __restrict__ A,
        const float* __restrict__ Wq, const float* __restrict__ bq, float* __restrict__ q,
        const float* __restrict__ Wk, const float* __restrict__ bk, float* __restrict__ k,
        const float* __restrict__ Wv, const float* __restrict__ bv, float* __restrict__ v) {
    __shared__ uint32_t Wh[64][68];
    __shared__ uint32_t Wl[64][68];
    int sel = blockIdx.y;
    const float* W = (sel == 0) ? Wq : (sel == 1) ? Wk : Wv;
    const float* bb = (sel == 0) ? bq : (sel == 1) ? bk : bv;
    float* C = (sel == 0) ? q : (sel == 1) ? k : v;
    int m0 = (blockIdx.x >> 1) * 64;
    int n0 = (blockIdx.x & 1) * 64;
    gemm_body<3>(Wh, Wl, A, W, bb, nullptr, C, m0, n0);
}

// -------------------- flash attention, split-bf16 mma.sync ---------------------
// grid 256 = 16 bh x 16 q-chunks(128); 8 warps x 16 q-rows.
// Scores in log2 domain (scale includes log2 e), exp2f softmax.
__global__ __launch_bounds__(256) void attn_kernel(
        const float* __restrict__ Q, const float* __restrict__ K,
        const float* __restrict__ V, float* __restrict__ ctx) {
    __shared__ uint32_t Ksh[64 * 17];
    __shared__ uint32_t Ksl[64 * 17];
    __shared__ uint32_t Vth[32 * 33];
    __shared__ uint32_t Vtl[32 * 33];

    int bid = blockIdx.x;
    int bh  = bid >> 4;            // 0..15
    int qc  = bid & 15;            // 0..15
    int q0  = qc * 128;
    int tid = threadIdx.x;
    int w    = tid >> 5;           // 0..7
    int lane = tid & 31;
    int lq   = lane >> 2;
    int lr   = lane & 3;

    const float* Qg = Q + (size_t)bh * TT * 32;
    const float* Kg = K + (size_t)bh * TT * 32;
    const float* Vg = V + (size_t)bh * TT * 32;

    const float scale = 0.17677669529663687f * 1.4426950408889634f;  // 1/sqrt(32) * log2(e)
    int row0 = q0 + w * 16 + lq;

    uint32_t qh[2][4], ql[2][4];
    #pragma unroll
    for (int c2 = 0; c2 < 2; c2++) {
        #pragma unroll
        for (int r = 0; r < 4; r++) {
            int rr = row0 + ((r & 1) ? 8 : 0);
            int d  = c2 * 16 + 2 * lr + ((r >= 2) ? 8 : 0);
            float2 qv = *(const float2*)&Qg[(size_t)rr * 32 + d];
            split2(qv.x * scale, qv.y * scale, qh[c2][r], ql[c2][r]);
        }
    }

    float m0 = -1e30f, m1 = -1e30f, l0 = 0.f, l1 = 0.f;
    float o[4][4] = {};

    // staging regs: 256 threads cover the 64-key tile
    float4 kr[2];
    float2 vr0[2], vr1[2];
    int vj  = tid & 31;
    int vd0 = (tid >> 5) << 1;     // 0..14
    {
        #pragma unroll
        for (int p = 0; p < 2; p++) {
            int e = tid + p * 256;
            kr[p] = *(const float4*)&Kg[(size_t)(e >> 3) * 32 + (e & 7) * 4];
        }
        #pragma unroll
        for (int p = 0; p < 2; p++) {
            int d0 = vd0 + p * 16;
            vr0[p] = *(const float2*)&Vg[(size_t)(2 * vj) * 32 + d0];
            vr1[p] = *(const float2*)&Vg[(size_t)(2 * vj + 1) * 32 + d0];
        }
    }

    for (int tile = 0; tile < 32; tile++) {
        #pragma unroll
        for (int p = 0; p < 2; p++) {
            int e = tid + p * 256;
            int key = e >> 3, dq = e & 7;
            uint32_t h0, lo0, h1, lo1;
            split2(kr[p].x, kr[p].y, h0, lo0);
            split2(kr[p].z, kr[p].w, h1, lo1);
            Ksh[key * 17 + 2 * dq]     = h0;
            Ksh[key * 17 + 2 * dq + 1] = h1;
            Ksl[key * 17 + 2 * dq]     = lo0;
            Ksl[key * 17 + 2 * dq + 1] = lo1;
        }
        #pragma unroll
        for (int p = 0; p < 2; p++) {
            int d0 = vd0 + p * 16;
            float ax = __bfloat162float(__float2bfloat16(vr0[p].x));
            float bx = __bfloat162float(__float2bfloat16(vr1[p].x));
            float ay = __bfloat162float(__float2bfloat16(vr0[p].y));
            float by = __bfloat162float(__float2bfloat16(vr1[p].y));
            Vth[d0 * 33 + vj]       = pk_bf2(ax, bx);
            Vth[(d0 + 1) * 33 + vj] = pk_bf2(ay, by);
            Vtl[d0 * 33 + vj]       = pk_bf2(vr0[p].x - ax, vr1[p].x - bx);
            Vtl[(d0 + 1) * 33 + vj] = pk_bf2(vr0[p].y - ay, vr1[p].y - by);
        }
        __syncthreads();

        if (tile < 31) {
            int t0 = (tile + 1) * 64;
            #pragma unroll
            for (int p = 0; p < 2; p++) {
                int e = tid + p * 256;
                kr[p] = *(const float4*)&Kg[(size_t)(t0 + (e >> 3)) * 32 + (e & 7) * 4];
            }
            #pragma unroll
            for (int p = 0; p < 2; p++) {
                int d0 = vd0 + p * 16;
                vr0[p] = *(const float2*)&Vg[(size_t)(t0 + 2 * vj) * 32 + d0];
                vr1[p] = *(const float2*)&Vg[(size_t)(t0 + 2 * vj + 1) * 32 + d0];
            }
        }

        // ---- QK^T (scores already in log2 domain) ----
        float c[8][4] = {};
        #pragma unroll
        for (int nt = 0; nt < 8; nt++) {
            int key = nt * 8 + lq;
            const uint32_t* kh = &Ksh[key * 17 + lr];
            const uint32_t* kl = &Ksl[key * 17 + lr];
            #pragma unroll
            for (int kc = 0; kc < 2; kc++) {
                uint32_t bhf[2] = { kh[8 * kc], kh[8 * kc + 4] };
                uint32_t blf[2] = { kl[8 * kc], kl[8 * kc + 4] };
                mma16816(c[nt], qh[kc], bhf);
                mma16816(c[nt], qh[kc], blf);
                mma16816(c[nt], ql[kc], bhf);
            }
        }

        // ---- online softmax (base 2) ----
        float mx0 = -1e30f, mx1 = -1e30f;
        #pragma unroll
        for (int nt = 0; nt < 8; nt++) {
            mx0 = fmaxf(mx0, fmaxf(c[nt][0], c[nt][1]));
            mx1 = fmaxf(mx1, fmaxf(c[nt][2], c[nt][3]));
        }
        mx0 = fmaxf(mx0, __shfl_xor_sync(0xffffffff, mx0, 1));
        mx0 = fmaxf(mx0, __shfl_xor_sync(0xffffffff, mx0, 2));
        mx1 = fmaxf(mx1, __shfl_xor_sync(0xffffffff, mx1, 1));
        mx1 = fmaxf(mx1, __shfl_xor_sync(0xffffffff, mx1, 2));
        float nm0 = fmaxf(m0, mx0), nm1 = fmaxf(m1, mx1);
        float f0 = exp2f(m0 - nm0), f1 = exp2f(m1 - nm1);
        m0 = nm0; m1 = nm1;
        l0 *= f0; l1 *= f1;
        #pragma unroll
        for (int dt = 0; dt < 4; dt++) {
            o[dt][0] *= f0; o[dt][1] *= f0;
            o[dt][2] *= f1; o[dt][3] *= f1;
        }
        #pragma unroll
        for (int nt = 0; nt < 8; nt++) {
            c[nt][0] = exp2f(c[nt][0] - m0);
            c[nt][1] = exp2f(c[nt][1] - m0);
            c[nt][2] = exp2f(c[nt][2] - m1);
            c[nt][3] = exp2f(c[nt][3] - m1);
            l0 += c[nt][0] + c[nt][1];
            l1 += c[nt][2] + c[nt][3];
        }

        // ---- P @ V ----
        #pragma unroll
        for (int kc = 0; kc < 4; kc++) {
            uint32_t ah[4], al[4];
            split2(c[2*kc][0],   c[2*kc][1],   ah[0], al[0]);
            split2(c[2*kc][2],   c[2*kc][3],   ah[1], al[1]);
            split2(c[2*kc+1][0], c[2*kc+1][1], ah[2], al[2]);
            split2(c[2*kc+1][2], c[2*kc+1][3], ah[3], al[3]);
            #pragma unroll
            for (int dt = 0; dt < 4; dt++) {
                int d = dt * 8 + lq;
                const uint32_t* vh = &Vth[d * 33 + kc * 8 + lr];
                const uint32_t* vl = &Vtl[d * 33 + kc * 8 + lr];
                uint32_t bhf[2] = { vh[0], vh[4] };
                uint32_t blf[2] = { vl[0], vl[4] };
                mma16816(o[dt], ah, bhf);
                mma16816(o[dt], ah, blf);
                mma16816(o[dt], al, bhf);
            }
        }
        __syncthreads();
    }

    // ---- epilogue ----
    l0 += __shfl_xor_sync(0xffffffff, l0, 1);
    l0 += __shfl_xor_sync(0xffffffff, l0, 2);
    l1 += __shfl_xor_sync(0xffffffff, l1, 1);
    l1 += __shfl_xor_sync(0xffffffff, l1, 2);
    float inv0 = 1.0f / l0, inv1 = 1.0f / l1;
    int b = bh >> 2, hh = bh & 3;
    #pragma unroll
    for (int dt = 0; dt < 4; dt++) {
        int d = dt * 8 + 2 * lr;
        float2 v0 = { o[dt][0] * inv0, o[dt][1] * inv0 };
        float2 v1 = { o[dt][2] * inv1, o[dt][3] * inv1 };
        *(float2*)&ctx[(size_t)(b * TT + row0) * 128 + hh * 32 + d]       = v0;
        *(float2*)&ctx[(size_t)(b * TT + row0 + 8) * 128 + hh * 32 + d]   = v1;
    }
}

// -------------------- launch ---------------------------------------------------
extern "C" void kernel_launch(void* const* d_in, const int* in_sizes, int n_in,
                              void* d_out, int out_size) {
    const float* in  = (const float*)d_in[0];
    const float* Wq  = (const float*)d_in[1];
    const float* bq  = (const float*)d_in[2];
    const float* Wk  = (const float*)d_in[3];
    const float* bk  = (const float*)d_in[4];
    const float* Wv  = (const float*)d_in[5];
    const float* bv  = (const float*)d_in[6];
    const float* Wo  = (const float*)d_in[7];
    const float* bo  = (const float*)d_in[8];
    const float* W1  = (const float*)d_in[9];
    const float* b1  = (const float*)d_in[10];
    const float* W2  = (const float*)d_in[11];
    const float* b2  = (const float*)d_in[12];
    const float* lng = (const float*)d_in[13];
    const float* lnb = (const float*)d_in[14];
    float* out = (float*)d_out;

    float *h, *hn, *q, *k, *v, *ctx, *tmp, *pe;
    cudaGetSymbolAddress((void**)&h,   g_h);
    cudaGetSymbolAddress((void**)&hn,  g_hn);
    cudaGetSymbolAddress((void**)&q,   g_q);
    cudaGetSymbolAddress((void**)&k,   g_k);
    cudaGetSymbolAddress((void**)&v,   g_v);
    cudaGetSymbolAddress((void**)&ctx, g_ctx);
    cudaGetSymbolAddress((void**)&tmp, g_tmp);
    cudaGetSymbolAddress((void**)&pe,  g_pe);

    pe_kernel<<<128, 256>>>(pe);
    addpos_kernel<<<(ROWS * DD / 4) / 256, 256>>>(in, pe, h);

    for (int i = 0; i < NB; i++) {
        const float* Wqi = Wq + i * DD * DD; const float* bqi = bq + i * DD;
        const float* Wki = Wk + i * DD * DD; const float* bki = bk + i * DD;
        const float* Wvi = Wv + i * DD * DD; const float* bvi = bv + i * DD;
        const float* Woi = Wo + i * DD * DD; const float* boi = bo + i * DD;
        const float* W1i = W1 + i * DD * DD; const float* b1i = b1 + i * DD;
        const float* W2i = W2 + i * DD * DD; const float* b2i = b2 + i * DD;

        ln_kernel<<<ROWS / 8, 256>>>(h, lng + (2 * i) * DD, lnb + (2 * i) * DD, hn);
        qkv_mma_kernel<<<dim3(256, 3), 128>>>(hn, Wqi, bqi, q, Wki, bki, k, Wvi, bvi, v);
        attn_kernel<<<256, 256>>>(q, k, v, ctx);
        gemm_mma_kernel<0><<<256, 128>>>(ctx, Woi, boi, nullptr, h);
        ln_kernel<<<ROWS / 8, 256>>>(h, lng + (2 * i + 1) * DD, lnb + (2 * i + 1) * DD, hn);
        gemm_mma_kernel<1><<<256, 128>>>(hn, W1i, b1i, nullptr, tmp);
        gemm_mma_kernel<2><<<256, 128>>>(tmp, W2i, b2i, hn, h);
    }
    ln_kernel<<<ROWS / 8, 256>>>(h, lng + 3 * DD, lnb + 3 * DD, out);
}

// round 7
// speedup vs baseline: 3.2194x; 1.2723x over previous
#include <cuda_runtime.h>
#include <cuda_bf16.h>
#include <stdint.h>
#include <math.h>

#define NB 2
#define BB 4
#define TT 2048
#define DD 128
#define HH 4
#define DK 32
#define ROWS (BB*TT)          // 8192
#define LN_EPS 1e-3f

// -------------------- scratch (device globals; no allocs allowed) ------------
__device__ float g_h  [ROWS*DD];
__device__ float g_hn [ROWS*DD];
__device__ float g_v  [ROWS*DD];
__device__ float g_ctx[ROWS*DD];
__device__ float g_tmp[ROWS*DD];
__device__ float g_pe [TT*DD];
// split Q/K: [bh=16][t=2048][dp=16] = ROWS*64 words each (4 heads x 16 dp per row!)
__device__ uint32_t g_qh[ROWS*64], g_ql[ROWS*64];
__device__ uint32_t g_kh[ROWS*64], g_kl[ROWS*64];
__device__ uint32_t g_vh[16*32*1024], g_vl[16*32*1024];
__device__ uint32_t g_wh[6*NB*8192], g_wl[6*NB*8192];

// -------------------- split-bf16 helpers ---------------------------------------
__device__ __forceinline__ uint32_t pk_bf2(float a, float b) {
    __nv_bfloat162 t = __floats2bfloat162_rn(a, b);
    return *reinterpret_cast<uint32_t*>(&t);
}
__device__ __forceinline__ void split2(float a, float b, uint32_t& h, uint32_t& l) {
    float ah = __bfloat162float(__float2bfloat16(a));
    float bh = __bfloat162float(__float2bfloat16(b));
    h = pk_bf2(ah, bh);
    l = pk_bf2(a - ah, b - bh);
}
__device__ __forceinline__ void mma16816(float c[4], const uint32_t a[4], const uint32_t b[2]) {
    asm volatile(
        "mma.sync.aligned.m16n8k16.row.col.f32.bf16.bf16.f32 "
        "{%0,%1,%2,%3}, {%4,%5,%6,%7}, {%8,%9}, {%0,%1,%2,%3};\n"
        : "+f"(c[0]), "+f"(c[1]), "+f"(c[2]), "+f"(c[3])
        : "r"(a[0]), "r"(a[1]), "r"(a[2]), "r"(a[3]), "r"(b[0]), "r"(b[1]));
}

// -------------------- positional encoding -------------------------------------
__global__ void pe_kernel(float* __restrict__ pe) {
    int i = blockIdx.x;
    double f = exp(-((double)(2 * i) / 128.0) * 9.210340371976184);
    const double TWO_PI = 6.283185307179586;
    const double INV_TWO_PI = 0.15915494309189535;
    for (int t = threadIdx.x; t < TT; t += blockDim.x) {
        double ang = (double)t * f;
        double r = ang - TWO_PI * floor(ang * INV_TWO_PI);
        float rf = (float)r;
        pe[t * DD + i] = (i & 1) ? cosf(rf) : sinf(rf);
    }
}

__global__ void addpos_kernel(const float* __restrict__ in, const float* __restrict__ pe,
                              float* __restrict__ h) {
    int gi = blockIdx.x * blockDim.x + threadIdx.x;
    const float4* in4 = (const float4*)in;
    const float4* pe4 = (const float4*)pe;
    float4 a = in4[gi];
    float4 p = pe4[gi & ((TT * DD / 4) - 1)];
    a.x += p.x; a.y += p.y; a.z += p.z; a.w += p.w;
    ((float4*)h)[gi] = a;
}

// -------------------- LayerNorm --------------------------------------------------
__global__ void ln_kernel(const float* __restrict__ x, const float* __restrict__ g,
                          const float* __restrict__ b, float* __restrict__ y) {
    int row  = blockIdx.x * 8 + (threadIdx.x >> 5);
    int lane = threadIdx.x & 31;
    float4 xv = ((const float4*)x)[row * 32 + lane];
    float s = xv.x + xv.y + xv.z + xv.w;
    #pragma unroll
    for (int o = 16; o > 0; o >>= 1) s += __shfl_xor_sync(0xffffffff, s, o);
    float mu = s * (1.0f / 128.0f);
    float dx0 = xv.x - mu, dx1 = xv.y - mu, dx2 = xv.z - mu, dx3 = xv.w - mu;
    float sq = dx0*dx0 + dx1*dx1 + dx2*dx2 + dx3*dx3;
    #pragma unroll
    for (int o = 16; o > 0; o >>= 1) sq += __shfl_xor_sync(0xffffffff, sq, o);
    float var = sq * (1.0f / 128.0f);
    float r = rsqrtf(var + LN_EPS);
    float4 gv = ((const float4*)g)[lane];
    float4 bv = ((const float4*)b)[lane];
    float4 ov;
    ov.x = gv.x * dx0 * r + bv.x;
    ov.y = gv.y * dx1 * r + bv.y;
    ov.z = gv.z * dx2 * r + bv.z;
    ov.w = gv.w * dx3 * r + bv.w;
    ((float4*)y)[row * 32 + lane] = ov;
}

// -------------------- weight pre-split ------------------------------------------
__global__ void wsplit_kernel(const float* __restrict__ Wq, const float* __restrict__ Wk,
                              const float* __restrict__ Wv, const float* __restrict__ Wo,
                              const float* __restrict__ W1, const float* __restrict__ W2,
                              uint32_t* __restrict__ wh, uint32_t* __restrict__ wl) {
    const float* Ws[6] = {Wq, Wk, Wv, Wo, W1, W2};
    int fam = blockIdx.y;
    const float* W = Ws[fam];
    int idx = blockIdx.x * 256 + threadIdx.x;   // 0..16383 = NB*8192
    int layer = idx >> 13;
    int rem = idx & 8191;
    int kp = rem >> 7, n = rem & 127;
    const float* Wm = W + layer * 128 * 128;
    float w0 = Wm[(2 * kp) * 128 + n];
    float w1 = Wm[(2 * kp + 1) * 128 + n];
    uint32_t hi, lo;
    split2(w0, w1, hi, lo);
    int out = (fam * NB + layer) * 8192 + n * 64 + kp;
    wh[out] = hi;
    wl[out] = lo;
}

// -------------------- V transpose/split -----------------------------------------
// v fp32 [bh][t][32] -> Vh/Vl [bh][d 0..31][kp 0..1023] (key-pairs packed bf16x2)
__global__ void vprep_kernel(const float* __restrict__ v,
                             uint32_t* __restrict__ vh, uint32_t* __restrict__ vl) {
    int bh = blockIdx.x >> 5;
    int kp0 = (blockIdx.x & 31) * 32;
    const float* vb = v + (size_t)bh * 2048 * 32;
    uint32_t* th = vh + (size_t)bh * 32 * 1024;
    uint32_t* tl = vl + (size_t)bh * 32 * 1024;
    #pragma unroll
    for (int i = 0; i < 4; i++) {
        int idx = threadIdx.x + i * 256;   // 0..1023
        int d = idx >> 5;
        int kpl = idx & 31;
        float v0 = vb[(size_t)(2 * (kp0 + kpl)) * 32 + d];
        float v1 = vb[(size_t)(2 * (kp0 + kpl) + 1) * 32 + d];
        uint32_t hi, lo;
        split2(v0, v1, hi, lo);
        th[d * 1024 + kp0 + kpl] = hi;
        tl[d * 1024 + kp0 + kpl] = lo;
    }
}

// -------------------- tensor-core GEMM body -------------------------------------
// MODE: 0 plain fp32, 1 relu, 2 +residual, 3 fp32 scatter [B,H,T,DK],
//       4 split-bf16 d-pair output (scaled) into Ch/Cl [bh][t][16]
template <int MODE>
__device__ __forceinline__ void gemm_body(
        uint32_t (*Wh)[68], uint32_t (*Wl)[68],
        const float* __restrict__ A,
        const uint32_t* __restrict__ Wph, const uint32_t* __restrict__ Wpl,
        const float* __restrict__ bias, const float* __restrict__ R,
        float* __restrict__ C, uint32_t* __restrict__ Ch, uint32_t* __restrict__ Cl,
        float scl, int m0, int n0) {
    int tid = threadIdx.x;
    int w = tid >> 5, lane = tid & 31;
    int lq = lane >> 2, lr = lane & 3;

    // stage pre-split W tile: 64 n-rows x 64 kp, hi + lo (uint4 copies)
    #pragma unroll
    for (int i = 0; i < 8; i++) {
        int idx = tid + i * 128;           // 0..1023 uint4s
        int n = idx >> 4, u4 = (idx & 15) * 4;
        *(uint4*)&Wh[n][u4] = *(const uint4*)&Wph[(size_t)(n0 + n) * 64 + u4];
    }
    #pragma unroll
    for (int i = 0; i < 8; i++) {
        int idx = tid + i * 128;
        int n = idx >> 4, u4 = (idx & 15) * 4;
        *(uint4*)&Wl[n][u4] = *(const uint4*)&Wpl[(size_t)(n0 + n) * 64 + u4];
    }

    int mrow = m0 + w * 16 + lq;
    const float* Ar0 = &A[(size_t)mrow * 128];
    const float* Ar8 = Ar0 + 8 * 128;
    float acc[8][4] = {};

    float2 af[4];
    af[0] = *(const float2*)&Ar0[2 * lr];
    af[1] = *(const float2*)&Ar8[2 * lr];
    af[2] = *(const float2*)&Ar0[2 * lr + 8];
    af[3] = *(const float2*)&Ar8[2 * lr + 8];
    __syncthreads();

    #pragma unroll
    for (int kc = 0; kc < 8; kc++) {
        uint32_t ah[4], al[4];
        #pragma unroll
        for (int r = 0; r < 4; r++) split2(af[r].x, af[r].y, ah[r], al[r]);
        float2 af2[4];
        if (kc < 7) {
            int ko = (kc + 1) * 16;
            af2[0] = *(const float2*)&Ar0[ko + 2 * lr];
            af2[1] = *(const float2*)&Ar8[ko + 2 * lr];
            af2[2] = *(const float2*)&Ar0[ko + 2 * lr + 8];
            af2[3] = *(const float2*)&Ar8[ko + 2 * lr + 8];
        }
        #pragma unroll
        for (int nt = 0; nt < 8; nt++) {
            const uint32_t* ph = &Wh[nt * 8 + lq][kc * 8 + lr];
            const uint32_t* pl = &Wl[nt * 8 + lq][kc * 8 + lr];
            uint32_t bh2[2] = { ph[0], ph[4] };
            uint32_t bl2[2] = { pl[0], pl[4] };
            mma16816(acc[nt], ah, bh2);
            mma16816(acc[nt], ah, bl2);
            mma16816(acc[nt], al, bh2);
        }
        if (kc < 7) {
            af[0] = af2[0]; af[1] = af2[1]; af[2] = af2[2]; af[3] = af2[3];
        }
    }

    #pragma unroll
    for (int nt = 0; nt < 8; nt++) {
        int n = n0 + nt * 8 + 2 * lr;
        float2 bv = *(const float2*)&bias[n];
        float2 o0 = { acc[nt][0] + bv.x, acc[nt][1] + bv.y };
        float2 o1 = { acc[nt][2] + bv.x, acc[nt][3] + bv.y };
        if (MODE == 1) {
            o0.x = fmaxf(o0.x, 0.f); o0.y = fmaxf(o0.y, 0.f);
            o1.x = fmaxf(o1.x, 0.f); o1.y = fmaxf(o1.y, 0.f);
        }
        if (MODE == 2) {
            float2 r0 = *(const float2*)&R[(size_t)mrow * 128 + n];
            float2 r1 = *(const float2*)&R[(size_t)(mrow + 8) * 128 + n];
            o0.x += r0.x; o0.y += r0.y;
            o1.x += r1.x; o1.y += r1.y;
        }
        if (MODE == 3) {
            int hh = n >> 5, dk = n & 31;
            int b0i = mrow >> 11, t0i = mrow & 2047;
            *(float2*)&C[(((b0i << 2) + hh) * 2048 + t0i) * 32 + dk] = o0;
            int b1i = (mrow + 8) >> 11, t1i = (mrow + 8) & 2047;
            *(float2*)&C[(((b1i << 2) + hh) * 2048 + t1i) * 32 + dk] = o1;
        } else if (MODE == 4) {
            int hh = n >> 5, dp = (n & 31) >> 1;
            int b0i = mrow >> 11, t0i = mrow & 2047;
            uint32_t hi, lo;
            split2(o0.x * scl, o0.y * scl, hi, lo);
            size_t idx0 = ((size_t)((b0i << 2) + hh) * 2048 + t0i) * 16 + dp;
            Ch[idx0] = hi; Cl[idx0] = lo;
            int b1i = (mrow + 8) >> 11, t1i = (mrow + 8) & 2047;
            split2(o1.x * scl, o1.y * scl, hi, lo);
            size_t idx1 = ((size_t)((b1i << 2) + hh) * 2048 + t1i) * 16 + dp;
            Ch[idx1] = hi; Cl[idx1] = lo;
        } else {
            *(float2*)&C[(size_t)mrow * 128 + n] = o0;
            *(float2*)&C[(size_t)(mrow + 8) * 128 + n] = o1;
        }
    }
}

template <int MODE>
__global__ __launch_bounds__(128) void gemm_mma_kernel(
        const float* __restrict__ A,
        const uint32_t* __restrict__ Wph, const uint32_t* __restrict__ Wpl,
        const float* __restrict__ bias, const float* __restrict__ R,
        float* __restrict__ C) {
    __shared__ __align__(16) uint32_t Wh[64][68];
    __shared__ __align__(16) uint32_t Wl[64][68];
    int m0 = (blockIdx.x >> 1) * 64;
    int n0 = (blockIdx.x & 1) * 64;
    gemm_body<MODE>(Wh, Wl, A, Wph, Wpl, bias, R, C, nullptr, nullptr, 1.0f, m0, n0);
}

// fused Q/K/V: grid (256, 3). Q -> split(scaled), K -> split, V -> fp32 scatter.
__global__ __launch_bounds__(128) void qkv_mma_kernel(
        const float* __restrict__ A,
        const uint32_t* __restrict__ Wqh, const uint32_t* __restrict__ Wql, const float* __restrict__ bq,
        const uint32_t* __restrict__ Wkh, const uint32_t* __restrict__ Wkl, const float* __restrict__ bk,
        const uint32_t* __restrict__ Wvh, const uint32_t* __restrict__ Wvl, const float* __restrict__ bv,
        uint32_t* __restrict__ qh, uint32_t* __restrict__ ql,
        uint32_t* __restrict__ kh, uint32_t* __restrict__ kl,
        float* __restrict__ v) {
    __shared__ __align__(16) uint32_t Wh[64][68];
    __shared__ __align__(16) uint32_t Wl[64][68];
    int m0 = (blockIdx.x >> 1) * 64;
    int n0 = (blockIdx.x & 1) * 64;
    int sel = blockIdx.y;
    const float QSCL = 0.17677669529663687f * 1.4426950408889634f;  // 1/sqrt(32)*log2(e)
    if (sel == 0) {
        gemm_body<4>(Wh, Wl, A, Wqh, Wql, bq, nullptr, nullptr, qh, ql, QSCL, m0, n0);
    } else if (sel == 1) {
        gemm_body<4>(Wh, Wl, A, Wkh, Wkl, bk, nullptr, nullptr, kh, kl, 1.0f, m0, n0);
    } else {
        gemm_body<3>(Wh, Wl, A, Wvh, Wvl, bv, nullptr, v, nullptr, nullptr, 1.0f, m0, n0);
    }
}

// -------------------- flash attention (pre-split inputs) -------------------------
// grid 256 = 16 bh x 16 q-chunks(128); 8 warps x 16 q-rows. Pure copy + MMA loop.
__global__ __launch_bounds__(256) void attn_kernel(
        const uint32_t* __restrict__ Qh, const uint32_t* __restrict__ Ql,
        const uint32_t* __restrict__ Kh, const uint32_t* __restrict__ Kl,
        const uint32_t* __restrict__ Vh, const uint32_t* __restrict__ Vl,
        float* __restrict__ ctx) {
    __shared__ __align__(16) uint32_t Ksh[64 * 20];
    __shared__ __align__(16) uint32_t Ksl[64 * 20];
    __shared__ __align__(16) uint32_t Vsh[32 * 36];
    __shared__ __align__(16) uint32_t Vsl[32 * 36];

    int bid = blockIdx.x;
    int bh  = bid >> 4;
    int qc  = bid & 15;
    int q0  = qc * 128;
    int tid = threadIdx.x;
    int w    = tid >> 5;
    int lane = tid & 31;
    int lq   = lane >> 2;
    int lr   = lane & 3;
    int row0 = q0 + w * 16 + lq;

    const uint32_t* QhB = Qh + (size_t)bh * 2048 * 16;
    const uint32_t* QlB = Ql + (size_t)bh * 2048 * 16;
    const uint32_t* KhB = Kh + (size_t)bh * 2048 * 16;
    const uint32_t* KlB = Kl + (size_t)bh * 2048 * 16;
    const uint32_t* VhB = Vh + (size_t)bh * 32 * 1024;
    const uint32_t* VlB = Vl + (size_t)bh * 32 * 1024;

    uint32_t qh[2][4], ql[2][4];
    #pragma unroll
    for (int c2 = 0; c2 < 2; c2++) {
        #pragma unroll
        for (int r = 0; r < 4; r++) {
            int row = row0 + ((r & 1) ? 8 : 0);
            int dp = c2 * 8 + lr + ((r >= 2) ? 4 : 0);
            qh[c2][r] = QhB[(size_t)row * 16 + dp];
            ql[c2][r] = QlB[(size_t)row * 16 + dp];
        }
    }

    float m0 = -1e30f, m1 = -1e30f, l0 = 0.f, l1 = 0.f;
    float o[4][4] = {};

    int kkey = tid >> 2, kdq = (tid & 3) * 4;
    int vd = tid >> 3, vkp = (tid & 7) * 4;
    uint4 kh4, kl4, vh4, vl4;
    kh4 = *(const uint4*)&KhB[kkey * 16 + kdq];
    kl4 = *(const uint4*)&KlB[kkey * 16 + kdq];
    vh4 = *(const uint4*)&VhB[vd * 1024 + vkp];
    vl4 = *(const uint4*)&VlB[vd * 1024 + vkp];

    for (int tile = 0; tile < 32; tile++) {
        *(uint4*)&Ksh[kkey * 20 + kdq] = kh4;
        *(uint4*)&Ksl[kkey * 20 + kdq] = kl4;
        *(uint4*)&Vsh[vd * 36 + vkp] = vh4;
        *(uint4*)&Vsl[vd * 36 + vkp] = vl4;
        __syncthreads();

        if (tile < 31) {
            int t0 = (tile + 1) * 64, kp0 = (tile + 1) * 32;
            kh4 = *(const uint4*)&KhB[(size_t)(t0 + kkey) * 16 + kdq];
            kl4 = *(const uint4*)&KlB[(size_t)(t0 + kkey) * 16 + kdq];
            vh4 = *(const uint4*)&VhB[vd * 1024 + kp0 + vkp];
            vl4 = *(const uint4*)&VlB[vd * 1024 + kp0 + vkp];
        }

        // ---- QK^T (log2 domain; Q pre-scaled) ----
        float c[8][4] = {};
        #pragma unroll
        for (int nt = 0; nt < 8; nt++) {
            int key = nt * 8 + lq;
            const uint32_t* kh = &Ksh[key * 20 + lr];
            const uint32_t* kl = &Ksl[key * 20 + lr];
            #pragma unroll
            for (int kc = 0; kc < 2; kc++) {
                uint32_t bhf[2] = { kh[8 * kc], kh[8 * kc + 4] };
                uint32_t blf[2] = { kl[8 * kc], kl[8 * kc + 4] };
                mma16816(c[nt], qh[kc], bhf);
                mma16816(c[nt], qh[kc], blf);
                mma16816(c[nt], ql[kc], bhf);
            }
        }

        // ---- online softmax (base 2) ----
        float mx0 = -1e30f, mx1 = -1e30f;
        #pragma unroll
        for (int nt = 0; nt < 8; nt++) {
            mx0 = fmaxf(mx0, fmaxf(c[nt][0], c[nt][1]));
            mx1 = fmaxf(mx1, fmaxf(c[nt][2], c[nt][3]));
        }
        mx0 = fmaxf(mx0, __shfl_xor_sync(0xffffffff, mx0, 1));
        mx0 = fmaxf(mx0, __shfl_xor_sync(0xffffffff, mx0, 2));
        mx1 = fmaxf(mx1, __shfl_xor_sync(0xffffffff, mx1, 1));
        mx1 = fmaxf(mx1, __shfl_xor_sync(0xffffffff, mx1, 2));
        float nm0 = fmaxf(m0, mx0), nm1 = fmaxf(m1, mx1);
        float f0 = exp2f(m0 - nm0), f1 = exp2f(m1 - nm1);
        m0 = nm0; m1 = nm1;
        l0 *= f0; l1 *= f1;
        #pragma unroll
        for (int dt = 0; dt < 4; dt++) {
            o[dt][0] *= f0; o[dt][1] *= f0;
            o[dt][2] *= f1; o[dt][3] *= f1;
        }
        #pragma unroll
        for (int nt = 0; nt < 8; nt++) {
            c[nt][0] = exp2f(c[nt][0] - m0);
            c[nt][1] = exp2f(c[nt][1] - m0);
            c[nt][2] = exp2f(c[nt][2] - m1);
            c[nt][3] = exp2f(c[nt][3] - m1);
            l0 += c[nt][0] + c[nt][1];
            l1 += c[nt][2] + c[nt][3];
        }

        // ---- P @ V ----
        #pragma unroll
        for (int kc = 0; kc < 4; kc++) {
            uint32_t ah[4], al[4];
            split2(c[2*kc][0],   c[2*kc][1],   ah[0], al[0]);
            split2(c[2*kc][2],   c[2*kc][3],   ah[1], al[1]);
            split2(c[2*kc+1][0], c[2*kc+1][1], ah[2], al[2]);
            split2(c[2*kc+1][2], c[2*kc+1][3], ah[3], al[3]);
            #pragma unroll
            for (int dt = 0; dt < 4; dt++) {
                int d = dt * 8 + lq;
                const uint32_t* vh = &Vsh[d * 36 + kc * 8 + lr];
                const uint32_t* vl = &Vsl[d * 36 + kc * 8 + lr];
                uint32_t bhf[2] = { vh[0], vh[4] };
                uint32_t blf[2] = { vl[0], vl[4] };
                mma16816(o[dt], ah, bhf);
                mma16816(o[dt], ah, blf);
                mma16816(o[dt], al, bhf);
            }
        }
        __syncthreads();
    }

    // ---- epilogue ----
    l0 += __shfl_xor_sync(0xffffffff, l0, 1);
    l0 += __shfl_xor_sync(0xffffffff, l0, 2);
    l1 += __shfl_xor_sync(0xffffffff, l1, 1);
    l1 += __shfl_xor_sync(0xffffffff, l1, 2);
    float inv0 = 1.0f / l0, inv1 = 1.0f / l1;
    int b = bh >> 2, hh = bh & 3;
    #pragma unroll
    for (int dt = 0; dt < 4; dt++) {
        int d = dt * 8 + 2 * lr;
        float2 v0 = { o[dt][0] * inv0, o[dt][1] * inv0 };
        float2 v1 = { o[dt][2] * inv1, o[dt][3] * inv1 };
        *(float2*)&ctx[(size_t)(b * TT + row0) * 128 + hh * 32 + d]       = v0;
        *(float2*)&ctx[(size_t)(b * TT + row0 + 8) * 128 + hh * 32 + d]   = v1;
    }
}

// -------------------- launch ------------------------------------------------------
extern "C" void kernel_launch(void* const* d_in, const int* in_sizes, int n_in,
                              void* d_out, int out_size) {
    const float* in  = (const float*)d_in[0];
    const float* Wq  = (const float*)d_in[1];
    const float* bq  = (const float*)d_in[2];
    const float* Wk  = (const float*)d_in[3];
    const float* bk  = (const float*)d_in[4];
    const float* Wv  = (const float*)d_in[5];
    const float* bv  = (const float*)d_in[6];
    const float* Wo  = (const float*)d_in[7];
    const float* bo  = (const float*)d_in[8];
    const float* W1  = (const float*)d_in[9];
    const float* b1  = (const float*)d_in[10];
    const float* W2  = (const float*)d_in[11];
    const float* b2  = (const float*)d_in[12];
    const float* lng = (const float*)d_in[13];
    const float* lnb = (const float*)d_in[14];
    float* out = (float*)d_out;

    float *h, *hn, *v, *ctx, *tmp, *pe;
    uint32_t *qh, *ql, *kh, *kl, *vh, *vl, *wh, *wl;
    cudaGetSymbolAddress((void**)&h,   g_h);
    cudaGetSymbolAddress((void**)&hn,  g_hn);
    cudaGetSymbolAddress((void**)&v,   g_v);
    cudaGetSymbolAddress((void**)&ctx, g_ctx);
    cudaGetSymbolAddress((void**)&tmp, g_tmp);
    cudaGetSymbolAddress((void**)&pe,  g_pe);
    cudaGetSymbolAddress((void**)&qh,  g_qh);
    cudaGetSymbolAddress((void**)&ql,  g_ql);
    cudaGetSymbolAddress((void**)&kh,  g_kh);
    cudaGetSymbolAddress((void**)&kl,  g_kl);
    cudaGetSymbolAddress((void**)&vh,  g_vh);
    cudaGetSymbolAddress((void**)&vl,  g_vl);
    cudaGetSymbolAddress((void**)&wh,  g_wh);
    cudaGetSymbolAddress((void**)&wl,  g_wl);

    pe_kernel<<<128, 256>>>(pe);
    addpos_kernel<<<(ROWS * DD / 4) / 256, 256>>>(in, pe, h);
    wsplit_kernel<<<dim3(64, 6), 256>>>(Wq, Wk, Wv, Wo, W1, W2, wh, wl);

    for (int i = 0; i < NB; i++) {
        const uint32_t* Wqh = wh + (0 * NB + i) * 8192; const uint32_t* Wql = wl + (0 * NB + i) * 8192;
        const uint32_t* Wkh = wh + (1 * NB + i) * 8192; const uint32_t* Wkl = wl + (1 * NB + i) * 8192;
        const uint32_t* Wvh = wh + (2 * NB + i) * 8192; const uint32_t* Wvl = wl + (2 * NB + i) * 8192;
        const uint32_t* Woh = wh + (3 * NB + i) * 8192; const uint32_t* Wol = wl + (3 * NB + i) * 8192;
        const uint32_t* W1h = wh + (4 * NB + i) * 8192; const uint32_t* W1l = wl + (4 * NB + i) * 8192;
        const uint32_t* W2h = wh + (5 * NB + i) * 8192; const uint32_t* W2l = wl + (5 * NB + i) * 8192;
        const float* bqi = bq + i * DD;
        const float* bki = bk + i * DD;
        const float* bvi = bv + i * DD;
        const float* boi = bo + i * DD;
        const float* b1i = b1 + i * DD;
        const float* b2i = b2 + i * DD;

        ln_kernel<<<ROWS / 8, 256>>>(h, lng + (2 * i) * DD, lnb + (2 * i) * DD, hn);
        qkv_mma_kernel<<<dim3(256, 3), 128>>>(hn, Wqh, Wql, bqi, Wkh, Wkl, bki,
                                              Wvh, Wvl, bvi, qh, ql, kh, kl, v);
        vprep_kernel<<<512, 256>>>(v, vh, vl);
        attn_kernel<<<256, 256>>>(qh, ql, kh, kl, vh, vl, ctx);
        gemm_mma_kernel<0><<<256, 128>>>(ctx, Woh, Wol, boi, nullptr, h);
        ln_kernel<<<ROWS / 8, 256>>>(h, lng + (2 * i + 1) * DD, lnb + (2 * i + 1) * DD, hn);
        gemm_mma_kernel<1><<<256, 128>>>(hn, W1h, W1l, b1i, nullptr, tmp);
        gemm_mma_kernel<2><<<256, 128>>>(tmp, W2h, W2l, b2i, hn, h);
    }
    ln_kernel<<<ROWS / 8, 256>>>(h, lng + 3 * DD, lnb + 3 * DD, out);
}